// round 14
// baseline (speedup 1.0000x reference)
#include <cuda_runtime.h>
#include <cuda_bf16.h>

// BOWRegression: out[b] = sigmoid( sum_{distinct tok in text[:,b], tok != PAD} W[tok] + bias )
//
// text: [T=200, B=4096] token ids (int64 OR int32 -- detected at runtime)
// W:    [V=100000] float32,  b: [1] float32,  out: [B] float32
//
// One CTA = G=8 batch columns:
//   stage 1: coalesced load of 8x200 tokens into SMEM (8 tokens / 32B sector)
//   stage 2: warp w owns column w; dedup via per-column 512-entry SMEM hash
//            table (atomicCAS linear probe, key = tok+1, 0 = empty); the
//            inserting lane gathers W[tok].
//   stage 3: deterministic warp shuffle reduction, sigmoid, store.

#define T_TOK 200
#define BATCH 4096
#define PAD_TOK 1
#define NTHREADS 256
#define G 8          // columns per CTA (= warps per CTA)
#define HSZ 512      // hash slots per column (power of 2)

__global__ __launch_bounds__(NTHREADS, 4)
void bow_regression_kernel(const int* __restrict__ text32,
                           const float* __restrict__ W,
                           const float* __restrict__ bias,
                           float* __restrict__ out)
{
    __shared__ int      toks[G][T_TOK + 1];   // +1 pad -> conflict-free staging stores
    __shared__ unsigned table[G][HSZ];
    __shared__ int      is64_sh;

    const int b0  = blockIdx.x * G;
    const int tid = threadIdx.x;

    // ---- runtime dtype detection (int64 vs int32 token array) ----
    // int64 tokens store (low=value, high=0) -> all odd 32-bit words are 0.
    // For int32 random ids in [0,100000) the chance 32 odd words are all
    // zero is ~0. Deterministic for fixed inputs.
    if (tid == 0) {
        int all0 = 1;
        #pragma unroll
        for (int k = 1; k < 64; k += 2) all0 &= (text32[k] == 0);
        is64_sh = all0;
    }

    // ---- clear hash tables (4096 words / 256 threads = 16 stores) ----
    unsigned* tflat = &table[0][0];
    #pragma unroll
    for (int i = tid; i < G * HSZ; i += NTHREADS) tflat[i] = 0u;
    __syncthreads();

    const bool is64 = (is64_sh != 0);

    // ---- stage 1: coalesced token load, transpose into SMEM ----
    // element i -> (row t = i/8, col c = i%8); consecutive tid -> consecutive
    // column -> 8 tokens per 32B sector (int32) / 64B (int64).
    #pragma unroll
    for (int i = tid; i < G * T_TOK; i += NTHREADS) {
        const int t = i >> 3;
        const int c = i & (G - 1);
        const long long e = (long long)t * BATCH + b0 + c;
        const int tok = is64 ? text32[e * 2] : text32[e];
        toks[c][t] = tok;
    }
    __syncthreads();

    // ---- stage 2: per-warp column dedup + gather ----
    const int w    = tid >> 5;   // warp = column within group
    const int lane = tid & 31;

    float val = 0.0f;
    #pragma unroll
    for (int t = lane; t < T_TOK; t += 32) {
        const int tok = toks[w][t];
        if (tok != PAD_TOK) {
            const unsigned key  = (unsigned)tok + 1u;   // 0 reserved = empty
            unsigned       slot = ((unsigned)tok * 2654435761u) >> 23; // 9 bits
            for (;;) {
                const unsigned prev = atomicCAS(&table[w][slot], 0u, key);
                if (prev == 0u) { val += __ldg(&W[tok]); break; } // first insert owns it
                if (prev == key) break;                            // duplicate
                slot = (slot + 1) & (HSZ - 1);
            }
        }
    }

    // ---- stage 3: warp reduction + sigmoid ----
    #pragma unroll
    for (int o = 16; o > 0; o >>= 1)
        val += __shfl_down_sync(0xffffffffu, val, o);

    if (lane == 0) {
        const float s = val + bias[0];
        out[b0 + w] = 1.0f / (1.0f + expf(-s));
    }
}

extern "C" void kernel_launch(void* const* d_in, const int* in_sizes, int n_in,
                              void* d_out, int out_size)
{
    const int*   text = (const int*)d_in[0];
    const float* W    = (const float*)d_in[1];
    const float* bias = (const float*)d_in[2];
    float*       out  = (float*)d_out;

    bow_regression_kernel<<<BATCH / G, NTHREADS>>>(text, W, bias, out);
}

// round 15
// speedup vs baseline: 1.0128x; 1.0128x over previous
#include <cuda_runtime.h>
#include <cuda_bf16.h>

// BOWRegression: out[b] = sigmoid( sum_{distinct tok in text[:,b], tok != PAD} W[tok] + bias )
//
// text: [T=200, B=4096] token ids (int64 OR int32 -- detected at runtime)
// W:    [V=100000] float32,  b: [1] float32,  out: [B] float32
//
// One CTA = G=8 batch columns:
//   stage 1: coalesced load of 8x200 tokens into SMEM (8 tokens / 32B sector)
//   stage 2: warp w owns column w; dedup via per-column 512-entry SMEM hash
//            table (atomicCAS linear probe, key = tok+1, 0 = empty); the
//            inserting lane gathers W[tok].
//   stage 3: deterministic warp shuffle reduction, sigmoid, store.

#define T_TOK 200
#define BATCH 4096
#define PAD_TOK 1
#define NTHREADS 256
#define G 8          // columns per CTA (= warps per CTA)
#define HSZ 512      // hash slots per column (power of 2)

__global__ __launch_bounds__(NTHREADS, 4)
void bow_regression_kernel(const int* __restrict__ text32,
                           const float* __restrict__ W,
                           const float* __restrict__ bias,
                           float* __restrict__ out)
{
    __shared__ int      toks[G][T_TOK + 1];   // +1 pad -> conflict-free staging stores
    __shared__ unsigned table[G][HSZ];
    __shared__ int      is64_sh;

    const int b0  = blockIdx.x * G;
    const int tid = threadIdx.x;

    // ---- runtime dtype detection (int64 vs int32 token array) ----
    // int64 tokens store (low=value, high=0) -> all odd 32-bit words are 0.
    // For int32 random ids in [0,100000) the chance 32 odd words are all
    // zero is ~0. Deterministic for fixed inputs.
    if (tid == 0) {
        int all0 = 1;
        #pragma unroll
        for (int k = 1; k < 64; k += 2) all0 &= (text32[k] == 0);
        is64_sh = all0;
    }

    // ---- clear hash tables (4096 words / 256 threads = 16 stores) ----
    unsigned* tflat = &table[0][0];
    #pragma unroll
    for (int i = tid; i < G * HSZ; i += NTHREADS) tflat[i] = 0u;
    __syncthreads();

    const bool is64 = (is64_sh != 0);

    // ---- stage 1: coalesced token load, transpose into SMEM ----
    // element i -> (row t = i/8, col c = i%8); consecutive tid -> consecutive
    // column -> 8 tokens per 32B sector (int32) / 64B (int64).
    #pragma unroll
    for (int i = tid; i < G * T_TOK; i += NTHREADS) {
        const int t = i >> 3;
        const int c = i & (G - 1);
        const long long e = (long long)t * BATCH + b0 + c;
        const int tok = is64 ? text32[e * 2] : text32[e];
        toks[c][t] = tok;
    }
    __syncthreads();

    // ---- stage 2: per-warp column dedup + gather ----
    const int w    = tid >> 5;   // warp = column within group
    const int lane = tid & 31;

    float val = 0.0f;
    #pragma unroll
    for (int t = lane; t < T_TOK; t += 32) {
        const int tok = toks[w][t];
        if (tok != PAD_TOK) {
            const unsigned key  = (unsigned)tok + 1u;   // 0 reserved = empty
            unsigned       slot = ((unsigned)tok * 2654435761u) >> 23; // 9 bits
            for (;;) {
                const unsigned prev = atomicCAS(&table[w][slot], 0u, key);
                if (prev == 0u) { val += __ldg(&W[tok]); break; } // first insert owns it
                if (prev == key) break;                            // duplicate
                slot = (slot + 1) & (HSZ - 1);
            }
        }
    }

    // ---- stage 3: warp reduction + sigmoid ----
    #pragma unroll
    for (int o = 16; o > 0; o >>= 1)
        val += __shfl_down_sync(0xffffffffu, val, o);

    if (lane == 0) {
        const float s = val + bias[0];
        out[b0 + w] = 1.0f / (1.0f + expf(-s));
    }
}

extern "C" void kernel_launch(void* const* d_in, const int* in_sizes, int n_in,
                              void* d_out, int out_size)
{
    const int*   text = (const int*)d_in[0];
    const float* W    = (const float*)d_in[1];
    const float* bias = (const float*)d_in[2];
    float*       out  = (float*)d_out;

    bow_regression_kernel<<<BATCH / G, NTHREADS>>>(text, W, bias, out);
}